// round 1
// baseline (speedup 1.0000x reference)
#include <cuda_runtime.h>
#include <cstddef>

// Problem constants
#define KCLS 20
#define BB   2
#define TT   12
#define CC   10
#define HWSZ 16384          // 128*128
#define BT   24             // BB*TT
#define FEAT 4097
#define NH   128
#define NFC  32             // f-chunks of 128 covering 4096; f=4096 folded into bias
#define CHUNK 128

// Static device scratch (no allocations allowed)
__device__ float g_part[NFC * KCLS * BT * NH];  // GEMM1 partial sums, ~7.9MB
__device__ float g_A[KCLS * BT * CC];           // 1 + w  coefficient
__device__ float g_Bc[KCLS * BT * CC];          // b      coefficient

// ---------------------------------------------------------------------------
// Kernel 1: GEMM1 partials.  h1_pre[k, r, j] += sum_{f in chunk} feat[r,f]*W1[k,f,j]
// feat chunk fc (128 features) is a contiguous slab of att:
//   feat[r, fc*128 + q] = att[(fc>>1)*6144 + r*256 + (fc&1)*128 + q]
// Grid: (NFC, KCLS), 128 threads (one per j). Deterministic (no atomics).
// ---------------------------------------------------------------------------
__global__ __launch_bounds__(128) void gemm1_partial(
    const float* __restrict__ att, const float* __restrict__ W1)
{
    __shared__ float sf[BT * CHUNK];  // 12KB
    const int fc = blockIdx.x, k = blockIdx.y, tid = threadIdx.x;

    // Load att chunk into smem (float4)
    const float4* a4 = (const float4*)(att + (size_t)(fc >> 1) * (BT * 256) + (fc & 1) * 128);
    float4* s4 = (float4*)sf;
    #pragma unroll
    for (int i = tid; i < BT * CHUNK / 4; i += 128) {
        int r = i >> 5;       // 32 float4 per row
        int q = i & 31;
        s4[i] = a4[r * 64 + q];   // source row stride = 256 floats = 64 float4
    }
    __syncthreads();

    const int j = tid;
    float acc[BT];
    #pragma unroll
    for (int r = 0; r < BT; r++) acc[r] = 0.f;

    const float* w1p = W1 + ((size_t)k * FEAT + (size_t)fc * CHUNK) * NH + j;
    for (int f = 0; f < CHUNK; f += 4) {
        float w0 = w1p[(f + 0) * NH];
        float w1_ = w1p[(f + 1) * NH];
        float w2_ = w1p[(f + 2) * NH];
        float w3_ = w1p[(f + 3) * NH];
        #pragma unroll
        for (int r = 0; r < BT; r++) {
            float4 s = *(const float4*)&sf[r * CHUNK + f];
            acc[r] = fmaf(s.x, w0, acc[r]);
            acc[r] = fmaf(s.y, w1_, acc[r]);
            acc[r] = fmaf(s.z, w2_, acc[r]);
            acc[r] = fmaf(s.w, w3_, acc[r]);
        }
    }

    float* dst = g_part + (size_t)((fc * KCLS + k) * BT) * NH + j;
    #pragma unroll
    for (int r = 0; r < BT; r++) dst[r * NH] = acc[r];
}

// ---------------------------------------------------------------------------
// Kernel 2: reduce partials (+bias + date-feature term), relu, layer2, relu,
// layer3, emit A = 1+w and Bc = b coefficients.  One block per class k.
// ---------------------------------------------------------------------------
__global__ __launch_bounds__(128) void mlp_tail(
    const float* __restrict__ W1, const float* __restrict__ b1,
    const float* __restrict__ W2, const float* __restrict__ b2,
    const float* __restrict__ W3, const float* __restrict__ b3,
    const int* __restrict__ bp)
{
    __shared__ float s1[BT * NH];  // 12KB
    __shared__ float s2[BT * NH];  // 12KB
    const int k = blockIdx.x, j = threadIdx.x;

    // h1 = relu( b1 + pos*W1[:,4096,:] + sum_fc partial )
    const float biasj = b1[k * NH + j];
    const float wlast = W1[((size_t)k * FEAT + 4096) * NH + j];
    for (int r = 0; r < BT; r++) {
        float s = biasj + (float)bp[r] * wlast;
        #pragma unroll
        for (int fc = 0; fc < NFC; fc++)
            s += g_part[(size_t)((fc * KCLS + k) * BT + r) * NH + j];
        s1[r * NH + j] = fmaxf(s, 0.f);
    }
    __syncthreads();

    // layer 2: h2 = relu(h1 @ W2 + b2)
    float acc[BT];
    const float b2j = b2[k * NH + j];
    #pragma unroll
    for (int r = 0; r < BT; r++) acc[r] = b2j;
    const float* w2p = W2 + (size_t)k * NH * NH + j;
    for (int i = 0; i < NH; i += 4) {
        float w0 = w2p[(i + 0) * NH];
        float w1_ = w2p[(i + 1) * NH];
        float w2_ = w2p[(i + 2) * NH];
        float w3_ = w2p[(i + 3) * NH];
        #pragma unroll
        for (int r = 0; r < BT; r++) {
            float4 s = *(const float4*)&s1[r * NH + i];
            acc[r] = fmaf(s.x, w0, acc[r]);
            acc[r] = fmaf(s.y, w1_, acc[r]);
            acc[r] = fmaf(s.z, w2_, acc[r]);
            acc[r] = fmaf(s.w, w3_, acc[r]);
        }
    }
    #pragma unroll
    for (int r = 0; r < BT; r++) s2[r * NH + j] = fmaxf(acc[r], 0.f);
    __syncthreads();

    // layer 3: beta = h2 @ W3 + b3, emit coefficients
    for (int p = threadIdx.x; p < BT * 2 * CC; p += NH) {
        int r = p / (2 * CC);
        int o = p % (2 * CC);
        float a = b3[k * 2 * CC + o];
        const float* w3p = W3 + (size_t)k * NH * (2 * CC) + o;
        const float* hrow = &s2[r * NH];
        #pragma unroll 4
        for (int i = 0; i < NH; i++)
            a = fmaf(hrow[i], w3p[i * 2 * CC], a);
        int c = o >> 1;
        if ((o & 1) == 0) g_A [(k * BT + r) * CC + c] = 1.f + a;
        else              g_Bc[(k * BT + r) * CC + c] = a;
    }
}

// ---------------------------------------------------------------------------
// Kernel 3: per-pixel loss over K classes, argmin, write winning recon.
// Each thread handles 4 pixels (float4). Grid: (HW/512, C, B), 128 threads.
// loss_k (unnormalized) = sum_t (x_t - (A*m + B))^2 ; argmin invariant to 1/T.
// ---------------------------------------------------------------------------
__global__ __launch_bounds__(128) void classify_kernel(
    const float* __restrict__ input,
    const float* __restrict__ inten,
    float* __restrict__ out)
{
    __shared__ float sA[KCLS * TT];
    __shared__ float sB[KCLS * TT];
    const int c = blockIdx.y, b = blockIdx.z, tid = threadIdx.x;

    for (int i = tid; i < KCLS * TT; i += 128) {
        int k = i / TT, t = i % TT;
        sA[i] = g_A [(k * BT + b * TT + t) * CC + c];
        sB[i] = g_Bc[(k * BT + b * TT + t) * CC + c];
    }
    __syncthreads();

    const int hw4 = blockIdx.x * 128 + tid;      // index into HW/4 = 4096
    const float4* in4 = (const float4*)input;

    float4 x[TT];
    #pragma unroll
    for (int t = 0; t < TT; t++)
        x[t] = in4[(size_t)((b * TT + t) * CC + c) * (HWSZ / 4) + hw4];
    const float4 m = ((const float4*)inten)[b * (HWSZ / 4) + hw4];

    float best0 = 3.4e38f, best1 = 3.4e38f, best2 = 3.4e38f, best3 = 3.4e38f;
    int k0 = 0, k1 = 0, k2 = 0, k3 = 0;

    for (int k = 0; k < KCLS; k++) {
        float a0 = 0.f, a1 = 0.f, a2 = 0.f, a3 = 0.f;
        #pragma unroll
        for (int t = 0; t < TT; t++) {
            float a = sA[k * TT + t];
            float bb = sB[k * TT + t];
            float d;
            d = x[t].x - fmaf(a, m.x, bb); a0 = fmaf(d, d, a0);
            d = x[t].y - fmaf(a, m.y, bb); a1 = fmaf(d, d, a1);
            d = x[t].z - fmaf(a, m.z, bb); a2 = fmaf(d, d, a2);
            d = x[t].w - fmaf(a, m.w, bb); a3 = fmaf(d, d, a3);
        }
        if (a0 < best0) { best0 = a0; k0 = k; }
        if (a1 < best1) { best1 = a1; k1 = k; }
        if (a2 < best2) { best2 = a2; k2 = k; }
        if (a3 < best3) { best3 = a3; k3 = k; }
    }

    float4* o4 = (float4*)out;
    #pragma unroll
    for (int t = 0; t < TT; t++) {
        float4 o;
        o.x = fmaf(sA[k0 * TT + t], m.x, sB[k0 * TT + t]);
        o.y = fmaf(sA[k1 * TT + t], m.y, sB[k1 * TT + t]);
        o.z = fmaf(sA[k2 * TT + t], m.z, sB[k2 * TT + t]);
        o.w = fmaf(sA[k3 * TT + t], m.w, sB[k3 * TT + t]);
        o4[(size_t)((b * TT + t) * CC + c) * (HWSZ / 4) + hw4] = o;
    }
}

// ---------------------------------------------------------------------------
// Launch. Inputs (metadata order): input, batch_positions(int32), intensity_map,
// att, W1, b1, W2, b2, W3, b3.  Output: concat(output[B,T,C,H,W], intensity_map).
// ---------------------------------------------------------------------------
extern "C" void kernel_launch(void* const* d_in, const int* in_sizes, int n_in,
                              void* d_out, int out_size)
{
    const float* input = (const float*)d_in[0];
    const int*   bp    = (const int*)  d_in[1];
    const float* inten = (const float*)d_in[2];
    const float* att   = (const float*)d_in[3];
    const float* W1    = (const float*)d_in[4];
    const float* b1    = (const float*)d_in[5];
    const float* W2    = (const float*)d_in[6];
    const float* b2    = (const float*)d_in[7];
    const float* W3    = (const float*)d_in[8];
    const float* b3    = (const float*)d_in[9];
    float* out = (float*)d_out;

    gemm1_partial<<<dim3(NFC, KCLS), 128>>>(att, W1);
    mlp_tail<<<KCLS, NH>>>(W1, b1, W2, b2, W3, b3, bp);
    classify_kernel<<<dim3(HWSZ / 4 / 128, CC, BB), 128>>>(input, inten, out);

    // second tuple element: intensity_map copied verbatim
    cudaMemcpyAsync(out + (size_t)BB * TT * CC * HWSZ, inten,
                    (size_t)BB * HWSZ * sizeof(float),
                    cudaMemcpyDeviceToDevice);
}

// round 2
// speedup vs baseline: 1.1296x; 1.1296x over previous
#include <cuda_runtime.h>
#include <cstddef>

// Problem constants
#define KCLS 20
#define BB   2
#define TT   12
#define CC   10
#define HWSZ 16384          // 128*128
#define BT   24             // BB*TT
#define FEAT 4097
#define NH   128
#define CHUNK 64
#define NFC  64             // f-chunks of 64 covering 4096; f=4096 folded into bias

// Static device scratch (no allocations allowed)
__device__ float g_part[NFC * KCLS * BT * NH];  // GEMM1 partials, 15.7MB
__device__ float g_h1[KCLS * BT * NH];          // relu(layer1) 245KB
__device__ float g_A[KCLS * BT * CC];           // 1 + w  coefficient
__device__ float g_Bc[KCLS * BT * CC];          // b      coefficient

// ---------------------------------------------------------------------------
// Kernel 1: GEMM1 partials. h1_pre[k,r,j] partial over a 64-feature chunk.
// feat[r, fc*64+q] = att[(fc>>2)*(BT*256) + r*256 + (fc&3)*64 + q]
// Grid: (NFC=64, KCLS=20) = 1280 blocks, 128 threads (one per j).
// ---------------------------------------------------------------------------
__global__ __launch_bounds__(128, 8) void gemm1_partial(
    const float* __restrict__ att, const float* __restrict__ W1)
{
    __shared__ float sf[BT * CHUNK];  // 6KB
    const int fc = blockIdx.x, k = blockIdx.y, tid = threadIdx.x;

    // Load att chunk into smem (float4): 384 float4 over 128 threads
    const float4* a4 = (const float4*)(att + (size_t)(fc >> 2) * (BT * 256) + (fc & 3) * 64);
    float4* s4 = (float4*)sf;
    #pragma unroll
    for (int i = tid; i < BT * CHUNK / 4; i += 128) {
        int r = i >> 4;       // 16 float4 per row
        int q = i & 15;
        s4[i] = a4[r * 64 + q];   // source row stride = 256 floats
    }
    __syncthreads();

    const int j = tid;
    float acc[BT];
    #pragma unroll
    for (int r = 0; r < BT; r++) acc[r] = 0.f;

    const float* w1p = W1 + ((size_t)k * FEAT + (size_t)fc * CHUNK) * NH + j;
    for (int f = 0; f < CHUNK; f += 8) {
        float w[8];
        #pragma unroll
        for (int u = 0; u < 8; u++) w[u] = w1p[(f + u) * NH];
        #pragma unroll
        for (int r = 0; r < BT; r++) {
            float4 s0 = *(const float4*)&sf[r * CHUNK + f];
            float4 s1 = *(const float4*)&sf[r * CHUNK + f + 4];
            float a = acc[r];
            a = fmaf(s0.x, w[0], a);
            a = fmaf(s0.y, w[1], a);
            a = fmaf(s0.z, w[2], a);
            a = fmaf(s0.w, w[3], a);
            a = fmaf(s1.x, w[4], a);
            a = fmaf(s1.y, w[5], a);
            a = fmaf(s1.z, w[6], a);
            a = fmaf(s1.w, w[7], a);
            acc[r] = a;
        }
    }

    float* dst = g_part + (size_t)((fc * KCLS + k) * BT) * NH + j;
    #pragma unroll
    for (int r = 0; r < BT; r++) dst[r * NH] = acc[r];
}

// ---------------------------------------------------------------------------
// Kernel 2: wide reduction of partials + bias + date term + relu -> g_h1.
// 61440 outputs, one per thread. Coalesced in j; 64-deep MLP over fc.
// ---------------------------------------------------------------------------
__global__ __launch_bounds__(256) void reduce_h1(
    const float* __restrict__ W1, const float* __restrict__ b1,
    const int* __restrict__ bp)
{
    const int idx = blockIdx.x * 256 + threadIdx.x;  // (k*BT + r)*NH + j
    const int j = idx & (NH - 1);
    const int r = (idx >> 7) % BT;
    const int k = idx / (BT * NH);

    float s = b1[k * NH + j] + (float)bp[r] * W1[((size_t)k * FEAT + 4096) * NH + j];
    const float* p = g_part + (size_t)(k * BT + r) * NH + j;
    #pragma unroll 8
    for (int fc = 0; fc < NFC; fc++)
        s += p[(size_t)fc * (KCLS * BT * NH)];
    g_h1[idx] = fmaxf(s, 0.f);
}

// ---------------------------------------------------------------------------
// Kernel 3: layers 2+3 from g_h1, emit A = 1+w and Bc = b.
// Grid: (KCLS, 2) — each block handles 12 rows for one class.
// ---------------------------------------------------------------------------
#define RH 12
__global__ __launch_bounds__(128) void mlp_tail(
    const float* __restrict__ W2, const float* __restrict__ b2,
    const float* __restrict__ W3, const float* __restrict__ b3)
{
    __shared__ float s1[RH * NH];  // 6KB
    __shared__ float s2[RH * NH];  // 6KB
    const int k = blockIdx.x, rh = blockIdx.y, j = threadIdx.x;

    #pragma unroll
    for (int r = 0; r < RH; r++)
        s1[r * NH + j] = g_h1[(size_t)(k * BT + rh * RH + r) * NH + j];
    __syncthreads();

    // layer 2: h2 = relu(h1 @ W2 + b2)
    float acc[RH];
    const float b2j = b2[k * NH + j];
    #pragma unroll
    for (int r = 0; r < RH; r++) acc[r] = b2j;
    const float* w2p = W2 + (size_t)k * NH * NH + j;
    for (int i = 0; i < NH; i += 4) {
        float w0 = w2p[(i + 0) * NH];
        float w1_ = w2p[(i + 1) * NH];
        float w2_ = w2p[(i + 2) * NH];
        float w3_ = w2p[(i + 3) * NH];
        #pragma unroll
        for (int r = 0; r < RH; r++) {
            float4 s = *(const float4*)&s1[r * NH + i];
            acc[r] = fmaf(s.x, w0, acc[r]);
            acc[r] = fmaf(s.y, w1_, acc[r]);
            acc[r] = fmaf(s.z, w2_, acc[r]);
            acc[r] = fmaf(s.w, w3_, acc[r]);
        }
    }
    #pragma unroll
    for (int r = 0; r < RH; r++) s2[r * NH + j] = fmaxf(acc[r], 0.f);
    __syncthreads();

    // layer 3: beta = h2 @ W3 + b3 ; 240 outputs per block
    for (int p = threadIdx.x; p < RH * 2 * CC; p += NH) {
        int r = p / (2 * CC);
        int o = p % (2 * CC);
        float a = b3[k * 2 * CC + o];
        const float* w3p = W3 + (size_t)k * NH * (2 * CC) + o;
        const float* hrow = &s2[r * NH];
        #pragma unroll 8
        for (int i = 0; i < NH; i++)
            a = fmaf(hrow[i], w3p[i * 2 * CC], a);
        int c = o >> 1;
        int rg = rh * RH + r;
        if ((o & 1) == 0) g_A [(k * BT + rg) * CC + c] = 1.f + a;
        else              g_Bc[(k * BT + rg) * CC + c] = a;
    }
}

// ---------------------------------------------------------------------------
// Kernel 4: per-pixel loss over K classes, argmin, write winning recon.
// 1 pixel/thread -> 10240 warps for latency hiding. Grid (128, C, B) x 128.
// ---------------------------------------------------------------------------
__global__ __launch_bounds__(128) void classify_kernel(
    const float* __restrict__ input,
    const float* __restrict__ inten,
    float* __restrict__ out)
{
    __shared__ float sA[KCLS * TT];
    __shared__ float sB[KCLS * TT];
    const int c = blockIdx.y, b = blockIdx.z, tid = threadIdx.x;

    for (int i = tid; i < KCLS * TT; i += 128) {
        int k = i / TT, t = i % TT;
        sA[i] = g_A [(k * BT + b * TT + t) * CC + c];
        sB[i] = g_Bc[(k * BT + b * TT + t) * CC + c];
    }
    __syncthreads();

    const int hw = blockIdx.x * 128 + tid;

    float x[TT];
    #pragma unroll
    for (int t = 0; t < TT; t++)
        x[t] = input[(size_t)((b * TT + t) * CC + c) * HWSZ + hw];
    const float m = inten[b * HWSZ + hw];

    float best = 3.4e38f;
    int kb = 0;
    #pragma unroll
    for (int k = 0; k < KCLS; k++) {
        float acc = 0.f;
        #pragma unroll
        for (int t = 0; t < TT; t++) {
            float d = x[t] - fmaf(sA[k * TT + t], m, sB[k * TT + t]);
            acc = fmaf(d, d, acc);
        }
        if (acc < best) { best = acc; kb = k; }
    }

    #pragma unroll
    for (int t = 0; t < TT; t++)
        out[(size_t)((b * TT + t) * CC + c) * HWSZ + hw] =
            fmaf(sA[kb * TT + t], m, sB[kb * TT + t]);
}

// ---------------------------------------------------------------------------
// Launch. Inputs: input, batch_positions(int32), intensity_map, att,
// W1, b1, W2, b2, W3, b3. Output: concat(output[B,T,C,H,W], intensity_map).
// ---------------------------------------------------------------------------
extern "C" void kernel_launch(void* const* d_in, const int* in_sizes, int n_in,
                              void* d_out, int out_size)
{
    const float* input = (const float*)d_in[0];
    const int*   bp    = (const int*)  d_in[1];
    const float* inten = (const float*)d_in[2];
    const float* att   = (const float*)d_in[3];
    const float* W1    = (const float*)d_in[4];
    const float* b1    = (const float*)d_in[5];
    const float* W2    = (const float*)d_in[6];
    const float* b2    = (const float*)d_in[7];
    const float* W3    = (const float*)d_in[8];
    const float* b3    = (const float*)d_in[9];
    float* out = (float*)d_out;

    gemm1_partial<<<dim3(NFC, KCLS), 128>>>(att, W1);
    reduce_h1<<<KCLS * BT * NH / 256, 256>>>(W1, b1, bp);
    mlp_tail<<<dim3(KCLS, 2), NH>>>(W2, b2, W3, b3);
    classify_kernel<<<dim3(HWSZ / 128, CC, BB), 128>>>(input, inten, out);

    // second tuple element: intensity_map copied verbatim
    cudaMemcpyAsync(out + (size_t)BB * TT * CC * HWSZ, inten,
                    (size_t)BB * HWSZ * sizeof(float),
                    cudaMemcpyDeviceToDevice);
}

// round 3
// speedup vs baseline: 1.1875x; 1.0513x over previous
#include <cuda_runtime.h>
#include <cstddef>

// Problem constants
#define KCLS 20
#define BB   2
#define TT   12
#define CC   10
#define HWSZ 16384          // 128*128
#define BT   24             // BB*TT
#define FEAT 4097
#define NH   128
#define CHUNK 64
#define NFC  64             // f-chunks of 64 covering 4096; f=4096 folded into bias

// Static device scratch (no allocations allowed)
__device__ float g_part[NFC * KCLS * BT * NH];  // GEMM1 partials, 15.7MB
__device__ float g_h1[KCLS * BT * NH];          // relu(layer1) 245KB
__device__ float g_A[KCLS * BT * CC];           // 1 + w  coefficient
__device__ float g_Bc[KCLS * BT * CC];          // b      coefficient

// ---------------------------------------------------------------------------
// Kernel 1: GEMM1 partials with LDG.128 weight loads.
// Block = (fc, k). 128 threads = 32 j-quads x 4 row-groups (6 rows each).
// Each thread: acc[6] float4 over 64 features.
// ---------------------------------------------------------------------------
__global__ __launch_bounds__(128, 8) void gemm1_partial(
    const float* __restrict__ att, const float* __restrict__ W1)
{
    __shared__ float sf[BT * CHUNK];  // 6KB
    const int fc = blockIdx.x, k = blockIdx.y, tid = threadIdx.x;

    // Load att chunk into smem (float4): 384 float4 over 128 threads
    const float4* a4 = (const float4*)(att + (size_t)(fc >> 2) * (BT * 256) + (fc & 3) * 64);
    float4* s4 = (float4*)sf;
    #pragma unroll
    for (int i = tid; i < BT * CHUNK / 4; i += 128) {
        int r = i >> 4;       // 16 float4 per row
        int q = i & 15;
        s4[i] = a4[r * 64 + q];   // source row stride = 256 floats
    }
    __syncthreads();

    const int j4 = (tid & 31);        // float4 index into j (j = j4*4)
    const int rg = tid >> 5;          // row group 0..3 (rows rg*6 .. rg*6+5)

    float4 acc[6];
    #pragma unroll
    for (int rr = 0; rr < 6; rr++) acc[rr] = make_float4(0.f, 0.f, 0.f, 0.f);

    const float4* w4p = (const float4*)(W1 + ((size_t)k * FEAT + (size_t)fc * CHUNK) * NH) + j4;
    const float* sfr = &sf[rg * 6 * CHUNK];

    #pragma unroll 8
    for (int f = 0; f < CHUNK; f++) {
        float4 w = w4p[f * (NH / 4)];
        #pragma unroll
        for (int rr = 0; rr < 6; rr++) {
            float s = sfr[rr * CHUNK + f];
            acc[rr].x = fmaf(s, w.x, acc[rr].x);
            acc[rr].y = fmaf(s, w.y, acc[rr].y);
            acc[rr].z = fmaf(s, w.z, acc[rr].z);
            acc[rr].w = fmaf(s, w.w, acc[rr].w);
        }
    }

    float4* dst = (float4*)(g_part + (size_t)((fc * KCLS + k) * BT + rg * 6) * NH) + j4;
    #pragma unroll
    for (int rr = 0; rr < 6; rr++) dst[rr * (NH / 4)] = acc[rr];
}

// ---------------------------------------------------------------------------
// Kernel 2: wide reduction of partials + bias + date term + relu -> g_h1.
// ---------------------------------------------------------------------------
__global__ __launch_bounds__(256) void reduce_h1(
    const float* __restrict__ W1, const float* __restrict__ b1,
    const int* __restrict__ bp)
{
    const int idx = blockIdx.x * 256 + threadIdx.x;  // (k*BT + r)*NH + j
    const int j = idx & (NH - 1);
    const int r = (idx >> 7) % BT;
    const int k = idx / (BT * NH);

    float s = b1[k * NH + j] + (float)bp[r] * W1[((size_t)k * FEAT + 4096) * NH + j];
    const float* p = g_part + (size_t)(k * BT + r) * NH + j;
    #pragma unroll 8
    for (int fc = 0; fc < NFC; fc++)
        s += p[(size_t)fc * (KCLS * BT * NH)];
    g_h1[idx] = fmaxf(s, 0.f);
}

// ---------------------------------------------------------------------------
// Kernel 3: layers 2+3 from g_h1, emit A = 1+w and Bc = b.
// Grid: (KCLS, 2) — each block handles 12 rows for one class.
// ---------------------------------------------------------------------------
#define RH 12
__global__ __launch_bounds__(128) void mlp_tail(
    const float* __restrict__ W2, const float* __restrict__ b2,
    const float* __restrict__ W3, const float* __restrict__ b3)
{
    __shared__ float s1[RH * NH];  // 6KB
    __shared__ float s2[RH * NH];  // 6KB
    const int k = blockIdx.x, rh = blockIdx.y, j = threadIdx.x;

    #pragma unroll
    for (int r = 0; r < RH; r++)
        s1[r * NH + j] = g_h1[(size_t)(k * BT + rh * RH + r) * NH + j];
    __syncthreads();

    // layer 2: h2 = relu(h1 @ W2 + b2)
    float acc[RH];
    const float b2j = b2[k * NH + j];
    #pragma unroll
    for (int r = 0; r < RH; r++) acc[r] = b2j;
    const float* w2p = W2 + (size_t)k * NH * NH + j;
    for (int i = 0; i < NH; i += 4) {
        float w0 = w2p[(i + 0) * NH];
        float w1_ = w2p[(i + 1) * NH];
        float w2_ = w2p[(i + 2) * NH];
        float w3_ = w2p[(i + 3) * NH];
        #pragma unroll
        for (int r = 0; r < RH; r++) {
            float4 s = *(const float4*)&s1[r * NH + i];
            acc[r] = fmaf(s.x, w0, acc[r]);
            acc[r] = fmaf(s.y, w1_, acc[r]);
            acc[r] = fmaf(s.z, w2_, acc[r]);
            acc[r] = fmaf(s.w, w3_, acc[r]);
        }
    }
    #pragma unroll
    for (int r = 0; r < RH; r++) s2[r * NH + j] = fmaxf(acc[r], 0.f);
    __syncthreads();

    // layer 3: beta = h2 @ W3 + b3 ; 240 outputs per block
    for (int p = threadIdx.x; p < RH * 2 * CC; p += NH) {
        int r = p / (2 * CC);
        int o = p % (2 * CC);
        float a = b3[k * 2 * CC + o];
        const float* w3p = W3 + (size_t)k * NH * (2 * CC) + o;
        const float* hrow = &s2[r * NH];
        #pragma unroll 8
        for (int i = 0; i < NH; i++)
            a = fmaf(hrow[i], w3p[i * 2 * CC], a);
        int c = o >> 1;
        int rg = rh * RH + r;
        if ((o & 1) == 0) g_A [(k * BT + rg) * CC + c] = 1.f + a;
        else              g_Bc[(k * BT + rg) * CC + c] = a;
    }
}

// ---------------------------------------------------------------------------
// Kernel 4: per-pixel loss over K classes, argmin, write winning recon.
// 2 pixels/thread; coefficients packed as float4 in smem (6 LDS.128 per class
// amortized over 2 pixels). Same accumulation order as the passing kernel.
// Grid (HW/256, C, B) x 128 threads. Blocks with c==0 also write the
// intensity_map tail of the output (replaces the memcpy node).
// ---------------------------------------------------------------------------
__global__ __launch_bounds__(128) void classify_kernel(
    const float* __restrict__ input,
    const float* __restrict__ inten,
    float* __restrict__ out)
{
    __shared__ __align__(16) float sAB[KCLS][24];   // per k: a[12] then b[12]
    const int c = blockIdx.y, b = blockIdx.z, tid = threadIdx.x;

    for (int i = tid; i < KCLS * 24; i += 128) {
        int k = i / 24, o = i % 24;
        float v = (o < 12) ? g_A [(k * BT + b * TT + o     ) * CC + c]
                           : g_Bc[(k * BT + b * TT + (o-12)) * CC + c];
        sAB[k][o] = v;
    }
    __syncthreads();

    const int hw = blockIdx.x * 256 + tid * 2;

    float x0[TT], x1[TT];
    const float* inb = input + (size_t)(b * TT * CC + c) * HWSZ + hw;
    #pragma unroll
    for (int t = 0; t < TT; t++) {
        float2 v = *(const float2*)(inb + (size_t)t * CC * HWSZ);
        x0[t] = v.x; x1[t] = v.y;
    }
    const float2 mm = *(const float2*)(inten + b * HWSZ + hw);
    const float m0 = mm.x, m1 = mm.y;

    float best0 = 3.4e38f, best1 = 3.4e38f;
    int k0 = 0, k1 = 0;

    #pragma unroll 4
    for (int k = 0; k < KCLS; k++) {
        float a[12], bc[12];
        const float4* p = (const float4*)&sAB[k][0];
        float4 v;
        v = p[0]; a[0]=v.x; a[1]=v.y; a[2]=v.z; a[3]=v.w;
        v = p[1]; a[4]=v.x; a[5]=v.y; a[6]=v.z; a[7]=v.w;
        v = p[2]; a[8]=v.x; a[9]=v.y; a[10]=v.z; a[11]=v.w;
        v = p[3]; bc[0]=v.x; bc[1]=v.y; bc[2]=v.z; bc[3]=v.w;
        v = p[4]; bc[4]=v.x; bc[5]=v.y; bc[6]=v.z; bc[7]=v.w;
        v = p[5]; bc[8]=v.x; bc[9]=v.y; bc[10]=v.z; bc[11]=v.w;

        float acc0 = 0.f, acc1 = 0.f;
        #pragma unroll
        for (int t = 0; t < TT; t++) {
            float d0 = x0[t] - fmaf(a[t], m0, bc[t]);
            acc0 = fmaf(d0, d0, acc0);
            float d1 = x1[t] - fmaf(a[t], m1, bc[t]);
            acc1 = fmaf(d1, d1, acc1);
        }
        if (acc0 < best0) { best0 = acc0; k0 = k; }
        if (acc1 < best1) { best1 = acc1; k1 = k; }
    }

    float* ob = out + (size_t)(b * TT * CC + c) * HWSZ + hw;
    #pragma unroll
    for (int t = 0; t < TT; t++) {
        float2 o;
        o.x = fmaf(sAB[k0][t], m0, sAB[k0][12 + t]);
        o.y = fmaf(sAB[k1][t], m1, sAB[k1][12 + t]);
        *(float2*)(ob + (size_t)t * CC * HWSZ) = o;
    }

    // intensity_map tail (second tuple element), written once (c==0 blocks)
    if (blockIdx.y == 0) {
        float* tail = out + (size_t)BB * TT * CC * HWSZ + b * HWSZ + hw;
        *(float2*)tail = mm;
    }
}

// ---------------------------------------------------------------------------
// Launch. Inputs: input, batch_positions(int32), intensity_map, att,
// W1, b1, W2, b2, W3, b3. Output: concat(output[B,T,C,H,W], intensity_map).
// ---------------------------------------------------------------------------
extern "C" void kernel_launch(void* const* d_in, const int* in_sizes, int n_in,
                              void* d_out, int out_size)
{
    const float* input = (const float*)d_in[0];
    const int*   bp    = (const int*)  d_in[1];
    const float* inten = (const float*)d_in[2];
    const float* att   = (const float*)d_in[3];
    const float* W1    = (const float*)d_in[4];
    const float* b1    = (const float*)d_in[5];
    const float* W2    = (const float*)d_in[6];
    const float* b2    = (const float*)d_in[7];
    const float* W3    = (const float*)d_in[8];
    const float* b3    = (const float*)d_in[9];
    float* out = (float*)d_out;

    gemm1_partial<<<dim3(NFC, KCLS), 128>>>(att, W1);
    reduce_h1<<<KCLS * BT * NH / 256, 256>>>(W1, b1, bp);
    mlp_tail<<<dim3(KCLS, 2), NH>>>(W2, b2, W3, b3);
    classify_kernel<<<dim3(HWSZ / 256, CC, BB), 128>>>(input, inten, out);
}

// round 4
// speedup vs baseline: 1.2443x; 1.0479x over previous
#include <cuda_runtime.h>
#include <cstddef>

// Problem constants
#define KCLS 20
#define BB   2
#define TT   12
#define CC   10
#define HWSZ 16384          // 128*128
#define BT   24             // BB*TT
#define FEAT 4097
#define NH   128
#define CHUNK 128
#define NFC  32             // f-chunks of 128 covering 4096; f=4096 folded into bias

// Static device scratch (no allocations allowed)
__device__ float g_part[NFC * KCLS * BT * NH];  // GEMM1 partials, 7.9MB
__device__ float g_h1[KCLS * BT * NH];          // relu(layer1) 245KB
__device__ float g_A[KCLS * BT * CC];           // 1 + w  coefficient
__device__ float g_Bc[KCLS * BT * CC];          // b      coefficient

// ---------------------------------------------------------------------------
// Kernel 1: GEMM1 partials with LDG.128 weight loads.
// Block = (fc, k). 128 threads = 32 j-quads x 4 row-groups (6 rows each).
// ---------------------------------------------------------------------------
__global__ __launch_bounds__(128, 8) void gemm1_partial(
    const float* __restrict__ att, const float* __restrict__ W1)
{
    __shared__ float sf[BT * CHUNK];  // 12KB
    const int fc = blockIdx.x, k = blockIdx.y, tid = threadIdx.x;

    // feat[r, fc*128+q] = att[(fc>>1)*(BT*256) + r*256 + (fc&1)*128 + q]
    const float4* a4 = (const float4*)(att + (size_t)(fc >> 1) * (BT * 256) + (fc & 1) * 128);
    float4* s4 = (float4*)sf;
    #pragma unroll
    for (int i = tid; i < BT * CHUNK / 4; i += 128) {
        int r = i >> 5;          // 32 float4 per row
        int q = i & 31;
        s4[i] = a4[r * 64 + q];  // source row stride = 256 floats
    }
    __syncthreads();

    const int j4 = (tid & 31);   // float4 index into j
    const int rg = tid >> 5;     // row group 0..3 (rows rg*6 .. rg*6+5)

    float4 acc[6];
    #pragma unroll
    for (int rr = 0; rr < 6; rr++) acc[rr] = make_float4(0.f, 0.f, 0.f, 0.f);

    const float4* w4p = (const float4*)(W1 + ((size_t)k * FEAT + (size_t)fc * CHUNK) * NH) + j4;
    const float* sfr = &sf[rg * 6 * CHUNK];

    #pragma unroll 8
    for (int f = 0; f < CHUNK; f++) {
        float4 w = w4p[f * (NH / 4)];
        #pragma unroll
        for (int rr = 0; rr < 6; rr++) {
            float s = sfr[rr * CHUNK + f];
            acc[rr].x = fmaf(s, w.x, acc[rr].x);
            acc[rr].y = fmaf(s, w.y, acc[rr].y);
            acc[rr].z = fmaf(s, w.z, acc[rr].z);
            acc[rr].w = fmaf(s, w.w, acc[rr].w);
        }
    }

    float4* dst = (float4*)(g_part + (size_t)((fc * KCLS + k) * BT + rg * 6) * NH) + j4;
    #pragma unroll
    for (int rr = 0; rr < 6; rr++) dst[rr * (NH / 4)] = acc[rr];
}

// ---------------------------------------------------------------------------
// Kernel 2: wide reduction of partials + bias + date term + relu -> g_h1.
// ---------------------------------------------------------------------------
__global__ __launch_bounds__(256) void reduce_h1(
    const float* __restrict__ W1, const float* __restrict__ b1,
    const int* __restrict__ bp)
{
    const int idx = blockIdx.x * 256 + threadIdx.x;  // (k*BT + r)*NH + j
    const int j = idx & (NH - 1);
    const int r = (idx >> 7) % BT;
    const int k = idx / (BT * NH);

    float s = b1[k * NH + j] + (float)bp[r] * W1[((size_t)k * FEAT + 4096) * NH + j];
    const float* p = g_part + (size_t)(k * BT + r) * NH + j;
    #pragma unroll 8
    for (int fc = 0; fc < NFC; fc++)
        s += p[(size_t)fc * (KCLS * BT * NH)];
    g_h1[idx] = fmaxf(s, 0.f);
}

// ---------------------------------------------------------------------------
// Kernel 3: layers 2+3 from g_h1, emit A = 1+w and Bc = b.
// Grid: (KCLS, 2) — each block handles 12 rows for one class.
// ---------------------------------------------------------------------------
#define RH 12
__global__ __launch_bounds__(128) void mlp_tail(
    const float* __restrict__ W2, const float* __restrict__ b2,
    const float* __restrict__ W3, const float* __restrict__ b3)
{
    __shared__ float s1[RH * NH];  // 6KB
    __shared__ float s2[RH * NH];  // 6KB
    const int k = blockIdx.x, rh = blockIdx.y, j = threadIdx.x;

    #pragma unroll
    for (int r = 0; r < RH; r++)
        s1[r * NH + j] = g_h1[(size_t)(k * BT + rh * RH + r) * NH + j];
    __syncthreads();

    // layer 2: h2 = relu(h1 @ W2 + b2)
    float acc[RH];
    const float b2j = b2[k * NH + j];
    #pragma unroll
    for (int r = 0; r < RH; r++) acc[r] = b2j;
    const float* w2p = W2 + (size_t)k * NH * NH + j;
    for (int i = 0; i < NH; i += 4) {
        float w0 = w2p[(i + 0) * NH];
        float w1_ = w2p[(i + 1) * NH];
        float w2_ = w2p[(i + 2) * NH];
        float w3_ = w2p[(i + 3) * NH];
        #pragma unroll
        for (int r = 0; r < RH; r++) {
            float4 s = *(const float4*)&s1[r * NH + i];
            acc[r] = fmaf(s.x, w0, acc[r]);
            acc[r] = fmaf(s.y, w1_, acc[r]);
            acc[r] = fmaf(s.z, w2_, acc[r]);
            acc[r] = fmaf(s.w, w3_, acc[r]);
        }
    }
    #pragma unroll
    for (int r = 0; r < RH; r++) s2[r * NH + j] = fmaxf(acc[r], 0.f);
    __syncthreads();

    // layer 3: beta = h2 @ W3 + b3 ; 240 outputs per block
    for (int p = threadIdx.x; p < RH * 2 * CC; p += NH) {
        int r = p / (2 * CC);
        int o = p % (2 * CC);
        float a = b3[k * 2 * CC + o];
        const float* w3p = W3 + (size_t)k * NH * (2 * CC) + o;
        const float* hrow = &s2[r * NH];
        #pragma unroll 8
        for (int i = 0; i < NH; i++)
            a = fmaf(hrow[i], w3p[i * 2 * CC], a);
        int c = o >> 1;
        int rg = rh * RH + r;
        if ((o & 1) == 0) g_A [(k * BT + rg) * CC + c] = 1.f + a;
        else              g_Bc[(k * BT + rg) * CC + c] = a;
    }
}

// ---------------------------------------------------------------------------
// Kernel 4: per-pixel argmin via expanded loss.
//   loss_k (minus k-indep Sum x^2) = m^2*G1 + m*G2 + G3 - 2*(m*P + Q)
//   P = sum_t a_t x_t, Q = sum_t b_t x_t ; G precomputed per class in smem.
// 4 pixels/thread (float4). Grid (HW/512, C, B) x 128 threads.
// ---------------------------------------------------------------------------
__global__ __launch_bounds__(128) void classify_kernel(
    const float* __restrict__ input,
    const float* __restrict__ inten,
    float* __restrict__ out)
{
    __shared__ __align__(16) float sAB[KCLS][24];   // per k: a[12] then b[12]
    __shared__ float sG[KCLS][4];                   // G1, G2=2*sum(ab), G3
    const int c = blockIdx.y, b = blockIdx.z, tid = threadIdx.x;

    for (int i = tid; i < KCLS * 24; i += 128) {
        int k = i / 24, o = i % 24;
        sAB[k][o] = (o < 12) ? g_A [(k * BT + b * TT + o       ) * CC + c]
                             : g_Bc[(k * BT + b * TT + (o - 12)) * CC + c];
    }
    __syncthreads();
    if (tid < KCLS) {
        float g1 = 0.f, g2 = 0.f, g3 = 0.f;
        #pragma unroll
        for (int t = 0; t < TT; t++) {
            float a = sAB[tid][t], bb = sAB[tid][12 + t];
            g1 = fmaf(a, a, g1);
            g2 = fmaf(a, bb, g2);
            g3 = fmaf(bb, bb, g3);
        }
        sG[tid][0] = g1; sG[tid][1] = 2.f * g2; sG[tid][2] = g3;
    }
    __syncthreads();

    const int hw = blockIdx.x * 512 + tid * 4;
    const float* inb = input + (size_t)(b * TT * CC + c) * HWSZ + hw;

    float4 x[TT];
    #pragma unroll
    for (int t = 0; t < TT; t++)
        x[t] = *(const float4*)(inb + (size_t)t * CC * HWSZ);
    const float4 m = *(const float4*)(inten + b * HWSZ + hw);
    float4 m2;
    m2.x = m.x * m.x; m2.y = m.y * m.y; m2.z = m.z * m.z; m2.w = m.w * m.w;

    float best0 = 3.4e38f, best1 = 3.4e38f, best2 = 3.4e38f, best3 = 3.4e38f;
    int k0 = 0, k1 = 0, k2 = 0, k3 = 0;

    #pragma unroll 4
    for (int k = 0; k < KCLS; k++) {
        float a[12], bb[12];
        {
            const float4* p = (const float4*)&sAB[k][0];
            float4 v;
            v = p[0]; a[0]=v.x; a[1]=v.y; a[2]=v.z; a[3]=v.w;
            v = p[1]; a[4]=v.x; a[5]=v.y; a[6]=v.z; a[7]=v.w;
            v = p[2]; a[8]=v.x; a[9]=v.y; a[10]=v.z; a[11]=v.w;
            v = p[3]; bb[0]=v.x; bb[1]=v.y; bb[2]=v.z; bb[3]=v.w;
            v = p[4]; bb[4]=v.x; bb[5]=v.y; bb[6]=v.z; bb[7]=v.w;
            v = p[5]; bb[8]=v.x; bb[9]=v.y; bb[10]=v.z; bb[11]=v.w;
        }
        float4 P = make_float4(0.f, 0.f, 0.f, 0.f);
        float4 Q = make_float4(0.f, 0.f, 0.f, 0.f);
        #pragma unroll
        for (int t = 0; t < TT; t++) {
            P.x = fmaf(a[t], x[t].x, P.x);  Q.x = fmaf(bb[t], x[t].x, Q.x);
            P.y = fmaf(a[t], x[t].y, P.y);  Q.y = fmaf(bb[t], x[t].y, Q.y);
            P.z = fmaf(a[t], x[t].z, P.z);  Q.z = fmaf(bb[t], x[t].z, Q.z);
            P.w = fmaf(a[t], x[t].w, P.w);  Q.w = fmaf(bb[t], x[t].w, Q.w);
        }
        const float g1 = sG[k][0], g2 = sG[k][1], g3 = sG[k][2];
        float l, r;
        l = fmaf(m2.x, g1, fmaf(m.x, g2, g3)); r = fmaf(m.x, P.x, Q.x); l = fmaf(r, -2.f, l);
        if (l < best0) { best0 = l; k0 = k; }
        l = fmaf(m2.y, g1, fmaf(m.y, g2, g3)); r = fmaf(m.y, P.y, Q.y); l = fmaf(r, -2.f, l);
        if (l < best1) { best1 = l; k1 = k; }
        l = fmaf(m2.z, g1, fmaf(m.z, g2, g3)); r = fmaf(m.z, P.z, Q.z); l = fmaf(r, -2.f, l);
        if (l < best2) { best2 = l; k2 = k; }
        l = fmaf(m2.w, g1, fmaf(m.w, g2, g3)); r = fmaf(m.w, P.w, Q.w); l = fmaf(r, -2.f, l);
        if (l < best3) { best3 = l; k3 = k; }
    }

    float* ob = out + (size_t)(b * TT * CC + c) * HWSZ + hw;
    #pragma unroll
    for (int t = 0; t < TT; t++) {
        float4 o;
        o.x = fmaf(sAB[k0][t], m.x, sAB[k0][12 + t]);
        o.y = fmaf(sAB[k1][t], m.y, sAB[k1][12 + t]);
        o.z = fmaf(sAB[k2][t], m.z, sAB[k2][12 + t]);
        o.w = fmaf(sAB[k3][t], m.w, sAB[k3][12 + t]);
        *(float4*)(ob + (size_t)t * CC * HWSZ) = o;
    }

    // intensity_map tail (second tuple element), written once (c==0 blocks)
    if (blockIdx.y == 0) {
        float* tail = out + (size_t)BB * TT * CC * HWSZ + b * HWSZ + hw;
        *(float4*)tail = m;
    }
}

// ---------------------------------------------------------------------------
// Launch. Inputs: input, batch_positions(int32), intensity_map, att,
// W1, b1, W2, b2, W3, b3. Output: concat(output[B,T,C,H,W], intensity_map).
// ---------------------------------------------------------------------------
extern "C" void kernel_launch(void* const* d_in, const int* in_sizes, int n_in,
                              void* d_out, int out_size)
{
    const float* input = (const float*)d_in[0];
    const int*   bp    = (const int*)  d_in[1];
    const float* inten = (const float*)d_in[2];
    const float* att   = (const float*)d_in[3];
    const float* W1    = (const float*)d_in[4];
    const float* b1    = (const float*)d_in[5];
    const float* W2    = (const float*)d_in[6];
    const float* b2    = (const float*)d_in[7];
    const float* W3    = (const float*)d_in[8];
    const float* b3    = (const float*)d_in[9];
    float* out = (float*)d_out;

    gemm1_partial<<<dim3(NFC, KCLS), 128>>>(att, W1);
    reduce_h1<<<KCLS * BT * NH / 256, 256>>>(W1, b1, bp);
    mlp_tail<<<dim3(KCLS, 2), NH>>>(W2, b2, W3, b3);
    classify_kernel<<<dim3(HWSZ / 512, CC, BB), 128>>>(input, inten, out);
}

// round 5
// speedup vs baseline: 1.4932x; 1.2000x over previous
#include <cuda_runtime.h>
#include <cstddef>

// Problem constants
#define KCLS 20
#define BB   2
#define TT   12
#define CC   10
#define HWSZ 16384          // 128*128
#define BT   24             // BB*TT
#define FEAT 4097
#define NH   128
#define CHUNK 128
#define NFC  32             // f-chunks of 128 covering 4096; f=4096 folded into bias

// Static device scratch (no allocations allowed)
__device__ float g_part[NFC * KCLS * BT * NH];  // GEMM1 partials, 7.9MB
__device__ float g_A[KCLS * BT * CC];           // 1 + w  coefficient
__device__ float g_Bc[KCLS * BT * CC];          // b      coefficient

// ---------------------------------------------------------------------------
// Kernel 1: GEMM1 partials with LDG.128 weight loads.
// Block = (fc, k). 128 threads = 32 j-quads x 4 row-groups (6 rows each).
// ---------------------------------------------------------------------------
__global__ __launch_bounds__(128, 8) void gemm1_partial(
    const float* __restrict__ att, const float* __restrict__ W1)
{
    __shared__ float sf[BT * CHUNK];  // 12KB
    const int fc = blockIdx.x, k = blockIdx.y, tid = threadIdx.x;

    // feat[r, fc*128+q] = att[(fc>>1)*(BT*256) + r*256 + (fc&1)*128 + q]
    const float4* a4 = (const float4*)(att + (size_t)(fc >> 1) * (BT * 256) + (fc & 1) * 128);
    float4* s4 = (float4*)sf;
    #pragma unroll
    for (int i = tid; i < BT * CHUNK / 4; i += 128) {
        int r = i >> 5;          // 32 float4 per row
        int q = i & 31;
        s4[i] = a4[r * 64 + q];  // source row stride = 256 floats
    }
    __syncthreads();

    const int j4 = (tid & 31);   // float4 index into j
    const int rg = tid >> 5;     // row group 0..3 (rows rg*6 .. rg*6+5)

    float4 acc[6];
    #pragma unroll
    for (int rr = 0; rr < 6; rr++) acc[rr] = make_float4(0.f, 0.f, 0.f, 0.f);

    const float4* w4p = (const float4*)(W1 + ((size_t)k * FEAT + (size_t)fc * CHUNK) * NH) + j4;
    const float* sfr = &sf[rg * 6 * CHUNK];

    #pragma unroll 8
    for (int f = 0; f < CHUNK; f++) {
        float4 w = w4p[f * (NH / 4)];
        #pragma unroll
        for (int rr = 0; rr < 6; rr++) {
            float s = sfr[rr * CHUNK + f];
            acc[rr].x = fmaf(s, w.x, acc[rr].x);
            acc[rr].y = fmaf(s, w.y, acc[rr].y);
            acc[rr].z = fmaf(s, w.z, acc[rr].z);
            acc[rr].w = fmaf(s, w.w, acc[rr].w);
        }
    }

    float4* dst = (float4*)(g_part + (size_t)((fc * KCLS + k) * BT + rg * 6) * NH) + j4;
    #pragma unroll
    for (int rr = 0; rr < 6; rr++) dst[rr * (NH / 4)] = acc[rr];
}

// ---------------------------------------------------------------------------
// Kernel 2 (fused): per-(k, row-pair) block: reduce partials + bias + date
// term + relu  ->  layer2 (+relu)  ->  layer3 -> emit A, Bc.
// Grid (KCLS, 12) = 240 blocks x 128 threads. W2 re-reads hit L2 (1.3MB).
// Same accumulation order as the previous separate kernels.
// ---------------------------------------------------------------------------
#define RP 2   // rows per block
__global__ __launch_bounds__(128) void mlp_fused_tail(
    const float* __restrict__ W1, const float* __restrict__ b1,
    const float* __restrict__ W2, const float* __restrict__ b2,
    const float* __restrict__ W3, const float* __restrict__ b3,
    const int* __restrict__ bp)
{
    __shared__ float s1[RP * NH];
    __shared__ float s2[RP * NH];
    const int k = blockIdx.x, rh = blockIdx.y, j = threadIdx.x;

    // Phase A: h1 for rows rh*2, rh*2+1
    const float biasj = b1[k * NH + j];
    const float wlast = W1[((size_t)k * FEAT + 4096) * NH + j];
    #pragma unroll
    for (int rr = 0; rr < RP; rr++) {
        int r = rh * RP + rr;
        float s = biasj + (float)bp[r] * wlast;
        const float* p = g_part + (size_t)(k * BT + r) * NH + j;
        #pragma unroll 8
        for (int fc = 0; fc < NFC; fc++)
            s += p[(size_t)fc * (KCLS * BT * NH)];
        s1[rr * NH + j] = fmaxf(s, 0.f);
    }
    __syncthreads();

    // Phase B: layer 2 (h2 = relu(h1 @ W2 + b2))
    float acc[RP];
    const float b2j = b2[k * NH + j];
    #pragma unroll
    for (int rr = 0; rr < RP; rr++) acc[rr] = b2j;
    const float* w2p = W2 + (size_t)k * NH * NH + j;
    for (int i = 0; i < NH; i += 4) {
        float w0 = w2p[(i + 0) * NH];
        float w1_ = w2p[(i + 1) * NH];
        float w2_ = w2p[(i + 2) * NH];
        float w3_ = w2p[(i + 3) * NH];
        #pragma unroll
        for (int rr = 0; rr < RP; rr++) {
            float4 s = *(const float4*)&s1[rr * NH + i];
            acc[rr] = fmaf(s.x, w0, acc[rr]);
            acc[rr] = fmaf(s.y, w1_, acc[rr]);
            acc[rr] = fmaf(s.z, w2_, acc[rr]);
            acc[rr] = fmaf(s.w, w3_, acc[rr]);
        }
    }
    #pragma unroll
    for (int rr = 0; rr < RP; rr++) s2[rr * NH + j] = fmaxf(acc[rr], 0.f);
    __syncthreads();

    // Phase C: layer 3 (beta = h2 @ W3 + b3), 40 outputs
    if (threadIdx.x < RP * 2 * CC) {
        int p = threadIdx.x;
        int rr = p / (2 * CC);
        int o = p % (2 * CC);
        float a = b3[k * 2 * CC + o];
        const float* w3p = W3 + (size_t)k * NH * (2 * CC) + o;
        const float* hrow = &s2[rr * NH];
        #pragma unroll 8
        for (int i = 0; i < NH; i++)
            a = fmaf(hrow[i], w3p[i * 2 * CC], a);
        int c = o >> 1;
        int r = rh * RP + rr;
        if ((o & 1) == 0) g_A [(k * BT + r) * CC + c] = 1.f + a;
        else              g_Bc[(k * BT + r) * CC + c] = a;
    }
}

// ---------------------------------------------------------------------------
// Kernel 3: per-pixel argmin via expanded loss, 2 px/thread.
//   loss'_k = m^2*G1 + m*G2 + G3 - 2*(m*P + Q),  P = sum a_t x_t, Q = sum b_t x_t
// Grid (HW/256, C, B) x 128 threads, 6 blocks/SM via launch_bounds.
// ---------------------------------------------------------------------------
__global__ __launch_bounds__(128, 6) void classify_kernel(
    const float* __restrict__ input,
    const float* __restrict__ inten,
    float* __restrict__ out)
{
    __shared__ __align__(16) float sAB[KCLS][24];   // per k: a[12] then b[12]
    __shared__ __align__(16) float sG[KCLS][4];     // G1, 2*sum(ab), G3
    const int c = blockIdx.y, b = blockIdx.z, tid = threadIdx.x;

    for (int i = tid; i < KCLS * 24; i += 128) {
        int k = i / 24, o = i % 24;
        sAB[k][o] = (o < 12) ? g_A [(k * BT + b * TT + o       ) * CC + c]
                             : g_Bc[(k * BT + b * TT + (o - 12)) * CC + c];
    }
    __syncthreads();
    if (tid < KCLS) {
        float g1 = 0.f, g2 = 0.f, g3 = 0.f;
        #pragma unroll
        for (int t = 0; t < TT; t++) {
            float a = sAB[tid][t], bb = sAB[tid][12 + t];
            g1 = fmaf(a, a, g1);
            g2 = fmaf(a, bb, g2);
            g3 = fmaf(bb, bb, g3);
        }
        sG[tid][0] = g1; sG[tid][1] = 2.f * g2; sG[tid][2] = g3; sG[tid][3] = 0.f;
    }
    __syncthreads();

    const int hw = blockIdx.x * 256 + tid * 2;
    const float* inb = input + (size_t)(b * TT * CC + c) * HWSZ + hw;

    float x0[TT], x1[TT];
    #pragma unroll
    for (int t = 0; t < TT; t++) {
        float2 v = *(const float2*)(inb + (size_t)t * CC * HWSZ);
        x0[t] = v.x; x1[t] = v.y;
    }
    const float2 mm = *(const float2*)(inten + b * HWSZ + hw);
    const float m0 = mm.x, m1 = mm.y;
    const float m20 = m0 * m0, m21 = m1 * m1;

    float best0 = 3.4e38f, best1 = 3.4e38f;
    int k0 = 0, k1 = 0;

    #pragma unroll 2
    for (int k = 0; k < KCLS; k++) {
        float a[12], bb[12];
        {
            const float4* p = (const float4*)&sAB[k][0];
            float4 v;
            v = p[0]; a[0]=v.x; a[1]=v.y; a[2]=v.z; a[3]=v.w;
            v = p[1]; a[4]=v.x; a[5]=v.y; a[6]=v.z; a[7]=v.w;
            v = p[2]; a[8]=v.x; a[9]=v.y; a[10]=v.z; a[11]=v.w;
            v = p[3]; bb[0]=v.x; bb[1]=v.y; bb[2]=v.z; bb[3]=v.w;
            v = p[4]; bb[4]=v.x; bb[5]=v.y; bb[6]=v.z; bb[7]=v.w;
            v = p[5]; bb[8]=v.x; bb[9]=v.y; bb[10]=v.z; bb[11]=v.w;
        }
        float P0 = 0.f, Q0 = 0.f, P1 = 0.f, Q1 = 0.f;
        #pragma unroll
        for (int t = 0; t < TT; t++) {
            P0 = fmaf(a[t], x0[t], P0);  Q0 = fmaf(bb[t], x0[t], Q0);
            P1 = fmaf(a[t], x1[t], P1);  Q1 = fmaf(bb[t], x1[t], Q1);
        }
        const float4 g = *(const float4*)&sG[k][0];
        float l, r;
        l = fmaf(m20, g.x, fmaf(m0, g.y, g.z)); r = fmaf(m0, P0, Q0); l = fmaf(r, -2.f, l);
        if (l < best0) { best0 = l; k0 = k; }
        l = fmaf(m21, g.x, fmaf(m1, g.y, g.z)); r = fmaf(m1, P1, Q1); l = fmaf(r, -2.f, l);
        if (l < best1) { best1 = l; k1 = k; }
    }

    float* ob = out + (size_t)(b * TT * CC + c) * HWSZ + hw;
    #pragma unroll
    for (int t = 0; t < TT; t++) {
        float2 o;
        o.x = fmaf(sAB[k0][t], m0, sAB[k0][12 + t]);
        o.y = fmaf(sAB[k1][t], m1, sAB[k1][12 + t]);
        *(float2*)(ob + (size_t)t * CC * HWSZ) = o;
    }

    // intensity_map tail (second tuple element), written once (c==0 blocks)
    if (blockIdx.y == 0) {
        float* tail = out + (size_t)BB * TT * CC * HWSZ + b * HWSZ + hw;
        *(float2*)tail = mm;
    }
}

// ---------------------------------------------------------------------------
// Launch. Inputs: input, batch_positions(int32), intensity_map, att,
// W1, b1, W2, b2, W3, b3. Output: concat(output[B,T,C,H,W], intensity_map).
// ---------------------------------------------------------------------------
extern "C" void kernel_launch(void* const* d_in, const int* in_sizes, int n_in,
                              void* d_out, int out_size)
{
    const float* input = (const float*)d_in[0];
    const int*   bp    = (const int*)  d_in[1];
    const float* inten = (const float*)d_in[2];
    const float* att   = (const float*)d_in[3];
    const float* W1    = (const float*)d_in[4];
    const float* b1    = (const float*)d_in[5];
    const float* W2    = (const float*)d_in[6];
    const float* b2    = (const float*)d_in[7];
    const float* W3    = (const float*)d_in[8];
    const float* b3    = (const float*)d_in[9];
    float* out = (float*)d_out;

    gemm1_partial<<<dim3(NFC, KCLS), 128>>>(att, W1);
    mlp_fused_tail<<<dim3(KCLS, BT / RP), 128>>>(W1, b1, W2, b2, W3, b3, bp);
    classify_kernel<<<dim3(HWSZ / 256, CC, BB), 128>>>(input, inten, out);
}

// round 7
// speedup vs baseline: 1.5069x; 1.0092x over previous
#include <cuda_runtime.h>
#include <cstddef>

// Problem constants
#define KCLS 20
#define BB   2
#define TT   12
#define CC   10
#define HWSZ 16384          // 128*128
#define BT   24             // BB*TT
#define FEAT 4097
#define NH   128
#define CHUNK 64
#define NFC  64             // f-chunks of 64 covering 4096; f=4096 folded into bias

// Static device scratch (no allocations allowed)
__device__ float g_part[NFC * KCLS * BT * NH];  // GEMM1 partials, 15.7MB
__device__ float g_A[KCLS * BT * CC];           // 1 + w  coefficient
__device__ float g_Bc[KCLS * BT * CC];          // b      coefficient

// ---------------------------------------------------------------------------
// Kernel 1: GEMM1 partials with LDG.128 weight loads.
// Block = (fc, k), 1280 blocks for MLP/occupancy. 128 threads =
// 32 j-quads x 4 row-groups (6 rows each); acc[6] float4 over 64 features.
// ---------------------------------------------------------------------------
__global__ __launch_bounds__(128, 8) void gemm1_partial(
    const float* __restrict__ att, const float* __restrict__ W1)
{
    __shared__ float sf[BT * CHUNK];  // 6KB
    const int fc = blockIdx.x, k = blockIdx.y, tid = threadIdx.x;

    // feat[r, fc*64+q] = att[(fc>>2)*(BT*256) + r*256 + (fc&3)*64 + q]
    const float4* a4 = (const float4*)(att + (size_t)(fc >> 2) * (BT * 256) + (fc & 3) * 64);
    float4* s4 = (float4*)sf;
    #pragma unroll
    for (int i = tid; i < BT * CHUNK / 4; i += 128) {
        int r = i >> 4;          // 16 float4 per row
        int q = i & 15;
        s4[i] = a4[r * 64 + q];  // source row stride = 256 floats
    }
    __syncthreads();

    const int j4 = (tid & 31);   // float4 index into j
    const int rg = tid >> 5;     // row group 0..3 (rows rg*6 .. rg*6+5)

    float4 acc[6];
    #pragma unroll
    for (int rr = 0; rr < 6; rr++) acc[rr] = make_float4(0.f, 0.f, 0.f, 0.f);

    const float4* w4p = (const float4*)(W1 + ((size_t)k * FEAT + (size_t)fc * CHUNK) * NH) + j4;
    const float* sfr = &sf[rg * 6 * CHUNK];

    #pragma unroll 8
    for (int f = 0; f < CHUNK; f++) {
        float4 w = w4p[f * (NH / 4)];
        #pragma unroll
        for (int rr = 0; rr < 6; rr++) {
            float s = sfr[rr * CHUNK + f];
            acc[rr].x = fmaf(s, w.x, acc[rr].x);
            acc[rr].y = fmaf(s, w.y, acc[rr].y);
            acc[rr].z = fmaf(s, w.z, acc[rr].z);
            acc[rr].w = fmaf(s, w.w, acc[rr].w);
        }
    }

    float4* dst = (float4*)(g_part + (size_t)((fc * KCLS + k) * BT + rg * 6) * NH) + j4;
    #pragma unroll
    for (int rr = 0; rr < 6; rr++) dst[rr * (NH / 4)] = acc[rr];
}

// ---------------------------------------------------------------------------
// Kernel 2 (fused): per-(k, row) block: reduce partials + bias + date term
// + relu -> layer2 (+relu) -> layer3 -> emit A, Bc.
// Grid (KCLS, 24) = 480 blocks x 128 threads for partial-read bandwidth.
// ---------------------------------------------------------------------------
__global__ __launch_bounds__(128) void mlp_fused_tail(
    const float* __restrict__ W1, const float* __restrict__ b1,
    const float* __restrict__ W2, const float* __restrict__ b2,
    const float* __restrict__ W3, const float* __restrict__ b3,
    const int* __restrict__ bp)
{
    __shared__ float s1[NH];
    __shared__ float s2[NH];
    const int k = blockIdx.x, r = blockIdx.y, j = threadIdx.x;

    // Phase A: h1 for row r (sum 64 partial chunks)
    {
        float s = b1[k * NH + j] + (float)bp[r] * W1[((size_t)k * FEAT + 4096) * NH + j];
        const float* p = g_part + (size_t)(k * BT + r) * NH + j;
        #pragma unroll 8
        for (int fc = 0; fc < NFC; fc++)
            s += p[(size_t)fc * (KCLS * BT * NH)];
        s1[j] = fmaxf(s, 0.f);
    }
    __syncthreads();

    // Phase B: layer 2 (h2 = relu(h1 @ W2 + b2))
    float acc = b2[k * NH + j];
    const float* w2p = W2 + (size_t)k * NH * NH + j;
    for (int i = 0; i < NH; i += 4) {
        float w0 = w2p[(i + 0) * NH];
        float w1_ = w2p[(i + 1) * NH];
        float w2_ = w2p[(i + 2) * NH];
        float w3_ = w2p[(i + 3) * NH];
        float4 s = *(const float4*)&s1[i];
        acc = fmaf(s.x, w0, acc);
        acc = fmaf(s.y, w1_, acc);
        acc = fmaf(s.z, w2_, acc);
        acc = fmaf(s.w, w3_, acc);
    }
    s2[j] = fmaxf(acc, 0.f);
    __syncthreads();

    // Phase C: layer 3 (beta = h2 @ W3 + b3), 20 outputs of 2C
    if (threadIdx.x < 2 * CC) {
        int o = threadIdx.x;
        float a = b3[k * 2 * CC + o];
        const float* w3p = W3 + (size_t)k * NH * (2 * CC) + o;
        #pragma unroll 8
        for (int i = 0; i < NH; i++)
            a = fmaf(s2[i], w3p[i * 2 * CC], a);
        int c = o >> 1;
        if ((o & 1) == 0) g_A [(k * BT + r) * CC + c] = 1.f + a;
        else              g_Bc[(k * BT + r) * CC + c] = a;
    }
}

// ---------------------------------------------------------------------------
// Kernel 3: per-pixel argmin via expanded loss, 2 px/thread.
//   loss'_k = m^2*G1 + m*G2 + G3 - 2*(m*P + Q),  P = sum a_t x_t, Q = sum b_t x_t
// Grid (HW/256, C, B) x 128 threads, 6 blocks/SM via launch_bounds.
// ---------------------------------------------------------------------------
__global__ __launch_bounds__(128, 6) void classify_kernel(
    const float* __restrict__ input,
    const float* __restrict__ inten,
    float* __restrict__ out)
{
    __shared__ __align__(16) float sAB[KCLS][24];   // per k: a[12] then b[12]
    __shared__ __align__(16) float sG[KCLS][4];     // G1, 2*sum(ab), G3
    const int c = blockIdx.y, b = blockIdx.z, tid = threadIdx.x;

    for (int i = tid; i < KCLS * 24; i += 128) {
        int k = i / 24, o = i % 24;
        sAB[k][o] = (o < 12) ? g_A [(k * BT + b * TT + o       ) * CC + c]
                             : g_Bc[(k * BT + b * TT + (o - 12)) * CC + c];
    }
    __syncthreads();
    if (tid < KCLS) {
        float g1 = 0.f, g2 = 0.f, g3 = 0.f;
        #pragma unroll
        for (int t = 0; t < TT; t++) {
            float a = sAB[tid][t], bb = sAB[tid][12 + t];
            g1 = fmaf(a, a, g1);
            g2 = fmaf(a, bb, g2);
            g3 = fmaf(bb, bb, g3);
        }
        sG[tid][0] = g1; sG[tid][1] = 2.f * g2; sG[tid][2] = g3; sG[tid][3] = 0.f;
    }
    __syncthreads();

    const int hw = blockIdx.x * 256 + tid * 2;
    const float* inb = input + (size_t)(b * TT * CC + c) * HWSZ + hw;

    float x0[TT], x1[TT];
    #pragma unroll
    for (int t = 0; t < TT; t++) {
        float2 v = *(const float2*)(inb + (size_t)t * CC * HWSZ);
        x0[t] = v.x; x1[t] = v.y;
    }
    const float2 mm = *(const float2*)(inten + b * HWSZ + hw);
    const float m0 = mm.x, m1 = mm.y;
    const float m20 = m0 * m0, m21 = m1 * m1;

    float best0 = 3.4e38f, best1 = 3.4e38f;
    int k0 = 0, k1 = 0;

    #pragma unroll 2
    for (int k = 0; k < KCLS; k++) {
        float a[12], bb[12];
        {
            const float4* p = (const float4*)&sAB[k][0];
            float4 v;
            v = p[0]; a[0]=v.x; a[1]=v.y; a[2]=v.z; a[3]=v.w;
            v = p[1]; a[4]=v.x; a[5]=v.y; a[6]=v.z; a[7]=v.w;
            v = p[2]; a[8]=v.x; a[9]=v.y; a[10]=v.z; a[11]=v.w;
            v = p[3]; bb[0]=v.x; bb[1]=v.y; bb[2]=v.z; bb[3]=v.w;
            v = p[4]; bb[4]=v.x; bb[5]=v.y; bb[6]=v.z; bb[7]=v.w;
            v = p[5]; bb[8]=v.x; bb[9]=v.y; bb[10]=v.z; bb[11]=v.w;
        }
        float P0 = 0.f, Q0 = 0.f, P1 = 0.f, Q1 = 0.f;
        #pragma unroll
        for (int t = 0; t < TT; t++) {
            P0 = fmaf(a[t], x0[t], P0);  Q0 = fmaf(bb[t], x0[t], Q0);
            P1 = fmaf(a[t], x1[t], P1);  Q1 = fmaf(bb[t], x1[t], Q1);
        }
        const float4 g = *(const float4*)&sG[k][0];
        float l, r;
        l = fmaf(m20, g.x, fmaf(m0, g.y, g.z)); r = fmaf(m0, P0, Q0); l = fmaf(r, -2.f, l);
        if (l < best0) { best0 = l; k0 = k; }
        l = fmaf(m21, g.x, fmaf(m1, g.y, g.z)); r = fmaf(m1, P1, Q1); l = fmaf(r, -2.f, l);
        if (l < best1) { best1 = l; k1 = k; }
    }

    float* ob = out + (size_t)(b * TT * CC + c) * HWSZ + hw;
    #pragma unroll
    for (int t = 0; t < TT; t++) {
        float2 o;
        o.x = fmaf(sAB[k0][t], m0, sAB[k0][12 + t]);
        o.y = fmaf(sAB[k1][t], m1, sAB[k1][12 + t]);
        *(float2*)(ob + (size_t)t * CC * HWSZ) = o;
    }

    // intensity_map tail (second tuple element), written once (c==0 blocks)
    if (blockIdx.y == 0) {
        float* tail = out + (size_t)BB * TT * CC * HWSZ + b * HWSZ + hw;
        *(float2*)tail = mm;
    }
}

// ---------------------------------------------------------------------------
// Launch. Inputs: input, batch_positions(int32), intensity_map, att,
// W1, b1, W2, b2, W3, b3. Output: concat(output[B,T,C,H,W], intensity_map).
// ---------------------------------------------------------------------------
extern "C" void kernel_launch(void* const* d_in, const int* in_sizes, int n_in,
                              void* d_out, int out_size)
{
    const float* input = (const float*)d_in[0];
    const int*   bp    = (const int*)  d_in[1];
    const float* inten = (const float*)d_in[2];
    const float* att   = (const float*)d_in[3];
    const float* W1    = (const float*)d_in[4];
    const float* b1    = (const float*)d_in[5];
    const float* W2    = (const float*)d_in[6];
    const float* b2    = (const float*)d_in[7];
    const float* W3    = (const float*)d_in[8];
    const float* b3    = (const float*)d_in[9];
    float* out = (float*)d_out;

    gemm1_partial<<<dim3(NFC, KCLS), 128>>>(att, W1);
    mlp_fused_tail<<<dim3(KCLS, BT), 128>>>(W1, b1, W2, b2, W3, b3, bp);
    classify_kernel<<<dim3(HWSZ / 256, CC, BB), 128>>>(input, inten, out);
}

// round 8
// speedup vs baseline: 1.7802x; 1.1814x over previous
#include <cuda_runtime.h>
#include <cstddef>

// Problem constants
#define KCLS 20
#define BB   2
#define TT   12
#define CC   10
#define HWSZ 16384          // 128*128
#define BT   24             // BB*TT
#define FEAT 4097
#define NH   128
#define CHUNK 128
#define NFC  32             // f-chunks of 128 covering 4096; f=4096 folded into bias

// Static device scratch (no allocations allowed)
__device__ float g_part[NFC * KCLS * BT * NH];  // GEMM1 partials, 7.9MB
__device__ float g_A[KCLS * BT * CC];           // 1 + w  coefficient
__device__ float g_Bc[KCLS * BT * CC];          // b      coefficient

// ---------------------------------------------------------------------------
// Kernel 1: GEMM1 partials. 128-reg budget so 8 LDG.128 stay in flight.
// Block = (fc, k), 640 blocks. 128 threads = 32 j-quads x 4 row-groups
// (6 rows each). Inner loop: 8-feature octave = 8 LDG.128 (W1) +
// 12 LDS.128 (att) + 192 FMA.
// ---------------------------------------------------------------------------
__global__ __launch_bounds__(128, 4) void gemm1_partial(
    const float* __restrict__ att, const float* __restrict__ W1)
{
    __shared__ float sf[BT * CHUNK];  // 12KB
    const int fc = blockIdx.x, k = blockIdx.y, tid = threadIdx.x;

    // feat[r, fc*128+q] = att[(fc>>1)*(BT*256) + r*256 + (fc&1)*128 + q]
    const float4* a4 = (const float4*)(att + (size_t)(fc >> 1) * (BT * 256) + (fc & 1) * 128);
    float4* s4 = (float4*)sf;
    #pragma unroll
    for (int i = tid; i < BT * CHUNK / 4; i += 128) {
        int r = i >> 5;          // 32 float4 per row
        int q = i & 31;
        s4[i] = a4[r * 64 + q];  // source row stride = 256 floats
    }
    __syncthreads();

    const int j4 = (tid & 31);   // float4 index into j
    const int rg = tid >> 5;     // row group 0..3 (rows rg*6 .. rg*6+5)

    float4 acc[6];
    #pragma unroll
    for (int rr = 0; rr < 6; rr++) acc[rr] = make_float4(0.f, 0.f, 0.f, 0.f);

    const float4* w4p = (const float4*)(W1 + ((size_t)k * FEAT + (size_t)fc * CHUNK) * NH) + j4;
    const float* sfr = &sf[rg * 6 * CHUNK];

    #pragma unroll 1
    for (int f0 = 0; f0 < CHUNK; f0 += 8) {
        float4 w[8];
        #pragma unroll
        for (int u = 0; u < 8; u++) w[u] = w4p[(f0 + u) * (NH / 4)];

        #pragma unroll
        for (int rr = 0; rr < 6; rr++) {
            float4 s0 = *(const float4*)&sfr[rr * CHUNK + f0];
            float4 s1 = *(const float4*)&sfr[rr * CHUNK + f0 + 4];
            float4 a = acc[rr];
            a.x = fmaf(s0.x, w[0].x, a.x); a.y = fmaf(s0.x, w[0].y, a.y);
            a.z = fmaf(s0.x, w[0].z, a.z); a.w = fmaf(s0.x, w[0].w, a.w);
            a.x = fmaf(s0.y, w[1].x, a.x); a.y = fmaf(s0.y, w[1].y, a.y);
            a.z = fmaf(s0.y, w[1].z, a.z); a.w = fmaf(s0.y, w[1].w, a.w);
            a.x = fmaf(s0.z, w[2].x, a.x); a.y = fmaf(s0.z, w[2].y, a.y);
            a.z = fmaf(s0.z, w[2].z, a.z); a.w = fmaf(s0.z, w[2].w, a.w);
            a.x = fmaf(s0.w, w[3].x, a.x); a.y = fmaf(s0.w, w[3].y, a.y);
            a.z = fmaf(s0.w, w[3].z, a.z); a.w = fmaf(s0.w, w[3].w, a.w);
            a.x = fmaf(s1.x, w[4].x, a.x); a.y = fmaf(s1.x, w[4].y, a.y);
            a.z = fmaf(s1.x, w[4].z, a.z); a.w = fmaf(s1.x, w[4].w, a.w);
            a.x = fmaf(s1.y, w[5].x, a.x); a.y = fmaf(s1.y, w[5].y, a.y);
            a.z = fmaf(s1.y, w[5].z, a.z); a.w = fmaf(s1.y, w[5].w, a.w);
            a.x = fmaf(s1.z, w[6].x, a.x); a.y = fmaf(s1.z, w[6].y, a.y);
            a.z = fmaf(s1.z, w[6].z, a.z); a.w = fmaf(s1.z, w[6].w, a.w);
            a.x = fmaf(s1.w, w[7].x, a.x); a.y = fmaf(s1.w, w[7].y, a.y);
            a.z = fmaf(s1.w, w[7].z, a.z); a.w = fmaf(s1.w, w[7].w, a.w);
            acc[rr] = a;
        }
    }

    float4* dst = (float4*)(g_part + (size_t)((fc * KCLS + k) * BT + rg * 6) * NH) + j4;
    #pragma unroll
    for (int rr = 0; rr < 6; rr++) dst[rr * (NH / 4)] = acc[rr];
}

// ---------------------------------------------------------------------------
// Kernel 2 (fused): per-(k, row) block: reduce partials + bias + date term
// + relu -> layer2 (+relu) -> layer3 -> emit A, Bc.
// Grid (KCLS, 24) = 480 blocks x 128 threads.
// ---------------------------------------------------------------------------
__global__ __launch_bounds__(128) void mlp_fused_tail(
    const float* __restrict__ W1, const float* __restrict__ b1,
    const float* __restrict__ W2, const float* __restrict__ b2,
    const float* __restrict__ W3, const float* __restrict__ b3,
    const int* __restrict__ bp)
{
    __shared__ float s1[NH];
    __shared__ float s2[NH];
    const int k = blockIdx.x, r = blockIdx.y, j = threadIdx.x;

    // Phase A: h1 for row r (sum 32 partial chunks)
    {
        float s = b1[k * NH + j] + (float)bp[r] * W1[((size_t)k * FEAT + 4096) * NH + j];
        const float* p = g_part + (size_t)(k * BT + r) * NH + j;
        #pragma unroll 8
        for (int fc = 0; fc < NFC; fc++)
            s += p[(size_t)fc * (KCLS * BT * NH)];
        s1[j] = fmaxf(s, 0.f);
    }
    __syncthreads();

    // Phase B: layer 2 (h2 = relu(h1 @ W2 + b2))
    float acc = b2[k * NH + j];
    const float* w2p = W2 + (size_t)k * NH * NH + j;
    for (int i = 0; i < NH; i += 4) {
        float w0 = w2p[(i + 0) * NH];
        float w1_ = w2p[(i + 1) * NH];
        float w2_ = w2p[(i + 2) * NH];
        float w3_ = w2p[(i + 3) * NH];
        float4 s = *(const float4*)&s1[i];
        acc = fmaf(s.x, w0, acc);
        acc = fmaf(s.y, w1_, acc);
        acc = fmaf(s.z, w2_, acc);
        acc = fmaf(s.w, w3_, acc);
    }
    s2[j] = fmaxf(acc, 0.f);
    __syncthreads();

    // Phase C: layer 3 (beta = h2 @ W3 + b3), 20 outputs of 2C
    if (threadIdx.x < 2 * CC) {
        int o = threadIdx.x;
        float a = b3[k * 2 * CC + o];
        const float* w3p = W3 + (size_t)k * NH * (2 * CC) + o;
        #pragma unroll 8
        for (int i = 0; i < NH; i++)
            a = fmaf(s2[i], w3p[i * 2 * CC], a);
        int c = o >> 1;
        if ((o & 1) == 0) g_A [(k * BT + r) * CC + c] = 1.f + a;
        else              g_Bc[(k * BT + r) * CC + c] = a;
    }
}

// ---------------------------------------------------------------------------
// Kernel 3: per-pixel argmin via expanded loss, 2 px/thread.
//   loss'_k = m^2*G1 + m*G2 + G3 - 2*(m*P + Q),  P = sum a_t x_t, Q = sum b_t x_t
// Grid (HW/256, C, B) x 128 threads, 6 blocks/SM via launch_bounds.
// ---------------------------------------------------------------------------
__global__ __launch_bounds__(128, 6) void classify_kernel(
    const float* __restrict__ input,
    const float* __restrict__ inten,
    float* __restrict__ out)
{
    __shared__ __align__(16) float sAB[KCLS][24];   // per k: a[12] then b[12]
    __shared__ __align__(16) float sG[KCLS][4];     // G1, 2*sum(ab), G3
    const int c = blockIdx.y, b = blockIdx.z, tid = threadIdx.x;

    for (int i = tid; i < KCLS * 24; i += 128) {
        int k = i / 24, o = i % 24;
        sAB[k][o] = (o < 12) ? g_A [(k * BT + b * TT + o       ) * CC + c]
                             : g_Bc[(k * BT + b * TT + (o - 12)) * CC + c];
    }
    __syncthreads();
    if (tid < KCLS) {
        float g1 = 0.f, g2 = 0.f, g3 = 0.f;
        #pragma unroll
        for (int t = 0; t < TT; t++) {
            float a = sAB[tid][t], bb = sAB[tid][12 + t];
            g1 = fmaf(a, a, g1);
            g2 = fmaf(a, bb, g2);
            g3 = fmaf(bb, bb, g3);
        }
        sG[tid][0] = g1; sG[tid][1] = 2.f * g2; sG[tid][2] = g3; sG[tid][3] = 0.f;
    }
    __syncthreads();

    const int hw = blockIdx.x * 256 + tid * 2;
    const float* inb = input + (size_t)(b * TT * CC + c) * HWSZ + hw;

    float x0[TT], x1[TT];
    #pragma unroll
    for (int t = 0; t < TT; t++) {
        float2 v = *(const float2*)(inb + (size_t)t * CC * HWSZ);
        x0[t] = v.x; x1[t] = v.y;
    }
    const float2 mm = *(const float2*)(inten + b * HWSZ + hw);
    const float m0 = mm.x, m1 = mm.y;
    const float m20 = m0 * m0, m21 = m1 * m1;

    float best0 = 3.4e38f, best1 = 3.4e38f;
    int k0 = 0, k1 = 0;

    #pragma unroll 2
    for (int k = 0; k < KCLS; k++) {
        float a[12], bb[12];
        {
            const float4* p = (const float4*)&sAB[k][0];
            float4 v;
            v = p[0]; a[0]=v.x; a[1]=v.y; a[2]=v.z; a[3]=v.w;
            v = p[1]; a[4]=v.x; a[5]=v.y; a[6]=v.z; a[7]=v.w;
            v = p[2]; a[8]=v.x; a[9]=v.y; a[10]=v.z; a[11]=v.w;
            v = p[3]; bb[0]=v.x; bb[1]=v.y; bb[2]=v.z; bb[3]=v.w;
            v = p[4]; bb[4]=v.x; bb[5]=v.y; bb[6]=v.z; bb[7]=v.w;
            v = p[5]; bb[8]=v.x; bb[9]=v.y; bb[10]=v.z; bb[11]=v.w;
        }
        float P0 = 0.f, Q0 = 0.f, P1 = 0.f, Q1 = 0.f;
        #pragma unroll
        for (int t = 0; t < TT; t++) {
            P0 = fmaf(a[t], x0[t], P0);  Q0 = fmaf(bb[t], x0[t], Q0);
            P1 = fmaf(a[t], x1[t], P1);  Q1 = fmaf(bb[t], x1[t], Q1);
        }
        const float4 g = *(const float4*)&sG[k][0];
        float l, r;
        l = fmaf(m20, g.x, fmaf(m0, g.y, g.z)); r = fmaf(m0, P0, Q0); l = fmaf(r, -2.f, l);
        if (l < best0) { best0 = l; k0 = k; }
        l = fmaf(m21, g.x, fmaf(m1, g.y, g.z)); r = fmaf(m1, P1, Q1); l = fmaf(r, -2.f, l);
        if (l < best1) { best1 = l; k1 = k; }
    }

    float* ob = out + (size_t)(b * TT * CC + c) * HWSZ + hw;
    #pragma unroll
    for (int t = 0; t < TT; t++) {
        float2 o;
        o.x = fmaf(sAB[k0][t], m0, sAB[k0][12 + t]);
        o.y = fmaf(sAB[k1][t], m1, sAB[k1][12 + t]);
        *(float2*)(ob + (size_t)t * CC * HWSZ) = o;
    }

    // intensity_map tail (second tuple element), written once (c==0 blocks)
    if (blockIdx.y == 0) {
        float* tail = out + (size_t)BB * TT * CC * HWSZ + b * HWSZ + hw;
        *(float2*)tail = mm;
    }
}

// ---------------------------------------------------------------------------
// Launch. Inputs: input, batch_positions(int32), intensity_map, att,
// W1, b1, W2, b2, W3, b3. Output: concat(output[B,T,C,H,W], intensity_map).
// ---------------------------------------------------------------------------
extern "C" void kernel_launch(void* const* d_in, const int* in_sizes, int n_in,
                              void* d_out, int out_size)
{
    const float* input = (const float*)d_in[0];
    const int*   bp    = (const int*)  d_in[1];
    const float* inten = (const float*)d_in[2];
    const float* att   = (const float*)d_in[3];
    const float* W1    = (const float*)d_in[4];
    const float* b1    = (const float*)d_in[5];
    const float* W2    = (const float*)d_in[6];
    const float* b2    = (const float*)d_in[7];
    const float* W3    = (const float*)d_in[8];
    const float* b3    = (const float*)d_in[9];
    float* out = (float*)d_out;

    gemm1_partial<<<dim3(NFC, KCLS), 128>>>(att, W1);
    mlp_fused_tail<<<dim3(KCLS, BT), 128>>>(W1, b1, W2, b2, W3, b3, bp);
    classify_kernel<<<dim3(HWSZ / 256, CC, BB), 128>>>(input, inten, out);
}